// round 4
// baseline (speedup 1.0000x reference)
#include <cuda_runtime.h>
#include <cstdint>

// Problem constants (fixed by the reference)
#define BB 16
#define NN 8192
#define MM 2048
#define KK 32
#define CC 128

#define CTAS   1024
#define WARPS  (CTAS * 8)      // 8192 warps; 32768 bm / 8192 = exactly 4 per warp

// out layout: [pts (B*M*K*3 floats)] ++ [features (B*M*K*C floats)]
//
// Warp-autonomous design: each warp owns whole (b,m) groups. No smem, no
// __syncthreads — per bm, lane k holds index k in a register; feature-row
// indices are broadcast with __shfl_sync. 4 rows in flight per batch.
__global__ __launch_bounds__(256, 8)
void knn_gather_norm_v4_kernel(const float* __restrict__ input,      // [B,N,C]
                               const float* __restrict__ points,     // [B,N,3]
                               const float* __restrict__ next_pts,   // [B,M,3]
                               const int*   __restrict__ indices,    // [B,M,K]
                               float* __restrict__ out_pts,          // [B,M,K,3]
                               float* __restrict__ out_feat)         // [B,M,K,C]
{
    const int lane = threadIdx.x & 31;
    const int wg   = blockIdx.x * (blockDim.x >> 5) + (threadIdx.x >> 5);

    for (int bm = wg; bm < BB * MM; bm += WARPS) {
        const int b = bm / MM;

        // lane k holds neighbor index k for this bm (one coalesced 128B load)
        const int myidx = __ldg(&indices[(size_t)bm * KK + lane]);

        // ---- pts: all 32 lanes, lane = neighbor k ----
        {
            const float nx = __ldg(&next_pts[(size_t)bm * 3 + 0]);
            const float ny = __ldg(&next_pts[(size_t)bm * 3 + 1]);
            const float nz = __ldg(&next_pts[(size_t)bm * 3 + 2]);

            const float* p = points + ((size_t)b * NN + (size_t)myidx) * 3;
            const float dx = __ldg(&p[0]) - nx;
            const float dy = __ldg(&p[1]) - ny;
            const float dz = __ldg(&p[2]) - nz;

            float mx = dx * dx + dy * dy + dz * dz;
            #pragma unroll
            for (int o = 16; o > 0; o >>= 1)
                mx = fmaxf(mx, __shfl_xor_sync(0xffffffffu, mx, o));

            float maxi = sqrtf(mx);
            if (maxi == 0.0f) maxi = 1.0f;
            const float inv = 1.0f / maxi;

            float* o = out_pts + ((size_t)bm * KK + (size_t)lane) * 3;
            o[0] = dx * inv;
            o[1] = dy * inv;
            o[2] = dz * inv;
        }

        // ---- features: 32 rows, 4 in flight per batch ----
        const float4* __restrict__ in_b =
            reinterpret_cast<const float4*>(input + (size_t)b * NN * CC);
        float4* __restrict__ of =
            reinterpret_cast<float4*>(out_feat + (size_t)bm * KK * CC);

        #pragma unroll
        for (int r0 = 0; r0 < KK; r0 += 4) {
            const int j0 = __shfl_sync(0xffffffffu, myidx, r0 + 0);
            const int j1 = __shfl_sync(0xffffffffu, myidx, r0 + 1);
            const int j2 = __shfl_sync(0xffffffffu, myidx, r0 + 2);
            const int j3 = __shfl_sync(0xffffffffu, myidx, r0 + 3);

            const float4 v0 = __ldg(&in_b[(size_t)j0 * (CC / 4) + lane]);
            const float4 v1 = __ldg(&in_b[(size_t)j1 * (CC / 4) + lane]);
            const float4 v2 = __ldg(&in_b[(size_t)j2 * (CC / 4) + lane]);
            const float4 v3 = __ldg(&in_b[(size_t)j3 * (CC / 4) + lane]);

            of[(size_t)(r0 + 0) * (CC / 4) + lane] = v0;
            of[(size_t)(r0 + 1) * (CC / 4) + lane] = v1;
            of[(size_t)(r0 + 2) * (CC / 4) + lane] = v2;
            of[(size_t)(r0 + 3) * (CC / 4) + lane] = v3;
        }
    }
}

extern "C" void kernel_launch(void* const* d_in, const int* in_sizes, int n_in,
                              void* d_out, int out_size)
{
    const float* input    = (const float*)d_in[0];  // [B,N,C]
    const float* points   = (const float*)d_in[1];  // [B,N,3]
    const float* next_pts = (const float*)d_in[2];  // [B,M,3]
    const int*   indices  = (const int*)  d_in[3];  // [B,M,K]

    float* out_pts  = (float*)d_out;                         // B*M*K*3
    float* out_feat = out_pts + (size_t)BB * MM * KK * 3;    // B*M*K*C

    knn_gather_norm_v4_kernel<<<CTAS, 256>>>(input, points, next_pts, indices,
                                             out_pts, out_feat);
}

// round 5
// speedup vs baseline: 1.2782x; 1.2782x over previous
#include <cuda_runtime.h>
#include <cstdint>

// Problem constants (fixed by the reference)
#define BB 16
#define NN 8192
#define MM 2048
#define KK 32
#define CC 128

// out layout: [pts (B*M*K*3 floats)] ++ [features (B*M*K*C floats)]
// One CTA per (b, m). 256 threads = 8 warps.
//  - all 8 warps: copy 4 feature rows each; all 4 gather loads issued
//    back-to-back (MLP=4) into registers, then 4 plain STG.128 stores.
//  - warp 0: normalized relative coords for all K=32 neighbors (lane = k),
//    computed while the feature loads are in flight.
__global__ __launch_bounds__(256, 8)
void knn_gather_norm_v5_kernel(const float* __restrict__ input,      // [B,N,C]
                               const float* __restrict__ points,     // [B,N,3]
                               const float* __restrict__ next_pts,   // [B,M,3]
                               const int*   __restrict__ indices,    // [B,M,K]
                               float* __restrict__ out_pts,          // [B,M,K,3]
                               float* __restrict__ out_feat)         // [B,M,K,C]
{
    const int bm = blockIdx.x;            // 0 .. B*M-1
    const int b  = bm / MM;

    __shared__ int sidx[KK];

    const int tid  = threadIdx.x;
    const int wid  = tid >> 5;
    const int lane = tid & 31;

    if (tid < KK) {
        sidx[tid] = __ldg(&indices[(size_t)bm * KK + tid]);
    }
    __syncthreads();

    // ---- features: warp wid owns rows {wid, wid+8, wid+16, wid+24} ----
    const float4* __restrict__ in_b =
        reinterpret_cast<const float4*>(input + (size_t)b * NN * CC);

    const int i0 = sidx[wid +  0];
    const int i1 = sidx[wid +  8];
    const int i2 = sidx[wid + 16];
    const int i3 = sidx[wid + 24];

    // 4 independent gather loads in flight
    const float4 v0 = __ldg(&in_b[(size_t)i0 * (CC / 4) + lane]);
    const float4 v1 = __ldg(&in_b[(size_t)i1 * (CC / 4) + lane]);
    const float4 v2 = __ldg(&in_b[(size_t)i2 * (CC / 4) + lane]);
    const float4 v3 = __ldg(&in_b[(size_t)i3 * (CC / 4) + lane]);

    float4* __restrict__ of =
        reinterpret_cast<float4*>(out_feat + (size_t)bm * KK * CC);

    of[(size_t)(wid +  0) * (CC / 4) + lane] = v0;
    of[(size_t)(wid +  8) * (CC / 4) + lane] = v1;
    of[(size_t)(wid + 16) * (CC / 4) + lane] = v2;
    of[(size_t)(wid + 24) * (CC / 4) + lane] = v3;

    // ---- pts: warp 0, lane = neighbor k ----
    if (wid == 0) {
        const int k   = lane;
        const int idx = sidx[k];

        const float nx = __ldg(&next_pts[(size_t)bm * 3 + 0]);
        const float ny = __ldg(&next_pts[(size_t)bm * 3 + 1]);
        const float nz = __ldg(&next_pts[(size_t)bm * 3 + 2]);

        const float* p = points + ((size_t)b * NN + (size_t)idx) * 3;
        const float dx = __ldg(&p[0]) - nx;
        const float dy = __ldg(&p[1]) - ny;
        const float dz = __ldg(&p[2]) - nz;

        float mx = dx * dx + dy * dy + dz * dz;
        #pragma unroll
        for (int o = 16; o > 0; o >>= 1)
            mx = fmaxf(mx, __shfl_xor_sync(0xffffffffu, mx, o));

        float maxi = sqrtf(mx);
        if (maxi == 0.0f) maxi = 1.0f;
        const float inv = 1.0f / maxi;

        float* o = out_pts + ((size_t)bm * KK + (size_t)k) * 3;
        o[0] = dx * inv;
        o[1] = dy * inv;
        o[2] = dz * inv;
    }
}

extern "C" void kernel_launch(void* const* d_in, const int* in_sizes, int n_in,
                              void* d_out, int out_size)
{
    const float* input    = (const float*)d_in[0];  // [B,N,C]
    const float* points   = (const float*)d_in[1];  // [B,N,3]
    const float* next_pts = (const float*)d_in[2];  // [B,M,3]
    const int*   indices  = (const int*)  d_in[3];  // [B,M,K]

    float* out_pts  = (float*)d_out;                         // B*M*K*3
    float* out_feat = out_pts + (size_t)BB * MM * KK * 3;    // B*M*K*C

    const int grid = BB * MM;   // 32768 CTAs
    knn_gather_norm_v5_kernel<<<grid, 256>>>(input, points, next_pts, indices,
                                             out_pts, out_feat);
}

// round 6
// speedup vs baseline: 1.3163x; 1.0298x over previous
#include <cuda_runtime.h>
#include <cstdint>

// Problem constants (fixed by the reference)
#define BB 16
#define NN 8192
#define MM 2048
#define KK 32
#define CC 128

// out layout: [pts (B*M*K*3 floats)] ++ [features (B*M*K*C floats)]
//
// One CTA per (b, m). 256 threads = 8 warps. R1 structure (fastest so far)
// with the smem+__syncthreads index stage removed:
//  - each warp loads the 32 indices once, coalesced (lane k = index k),
//    and broadcasts per-row indices with __shfl_sync. No smem, no barrier.
//  - warp 0: normalized relative coords for all K=32 neighbors (lane = k).
//  - warp w copies rows {4w .. 4w+3}, interleaved load->store per row
//    (low MLP_p1 on purpose: front-batched LDGs increase cross-CTA
//    L1tex-queue spread at occ=8 and measurably hurt DRAM utilization).
__global__ __launch_bounds__(256, 8)
void knn_gather_norm_v6_kernel(const float* __restrict__ input,      // [B,N,C]
                               const float* __restrict__ points,     // [B,N,3]
                               const float* __restrict__ next_pts,   // [B,M,3]
                               const int*   __restrict__ indices,    // [B,M,K]
                               float* __restrict__ out_pts,          // [B,M,K,3]
                               float* __restrict__ out_feat)         // [B,M,K,C]
{
    const int bm = blockIdx.x;            // 0 .. B*M-1
    const int b  = bm / MM;

    const int tid  = threadIdx.x;
    const int wid  = tid >> 5;
    const int lane = tid & 31;

    // lane k holds neighbor index k for this bm (one coalesced 128B load)
    const int myidx = __ldg(&indices[(size_t)bm * KK + lane]);

    // ---- pts: warp 0, lane = neighbor k ----
    if (wid == 0) {
        const int idx = myidx;

        const float nx = __ldg(&next_pts[(size_t)bm * 3 + 0]);
        const float ny = __ldg(&next_pts[(size_t)bm * 3 + 1]);
        const float nz = __ldg(&next_pts[(size_t)bm * 3 + 2]);

        const float* p = points + ((size_t)b * NN + (size_t)idx) * 3;
        const float dx = __ldg(&p[0]) - nx;
        const float dy = __ldg(&p[1]) - ny;
        const float dz = __ldg(&p[2]) - nz;

        float mx = dx * dx + dy * dy + dz * dz;
        #pragma unroll
        for (int o = 16; o > 0; o >>= 1)
            mx = fmaxf(mx, __shfl_xor_sync(0xffffffffu, mx, o));

        float maxi = sqrtf(mx);
        if (maxi == 0.0f) maxi = 1.0f;
        const float inv = 1.0f / maxi;

        float* o = out_pts + ((size_t)bm * KK + (size_t)lane) * 3;
        o[0] = dx * inv;
        o[1] = dy * inv;
        o[2] = dz * inv;
    }

    // ---- features: warp wid owns rows {4*wid .. 4*wid+3}, interleaved ----
    const float* __restrict__ in_b = input + (size_t)b * NN * CC;
    float4* __restrict__ of =
        reinterpret_cast<float4*>(out_feat + (size_t)bm * KK * CC);

    #pragma unroll
    for (int j = 0; j < 4; ++j) {
        const int k   = 4 * wid + j;
        const int idx = __shfl_sync(0xffffffffu, myidx, k);
        const float4 v =
            __ldg(reinterpret_cast<const float4*>(in_b + (size_t)idx * CC) + lane);
        of[(size_t)k * (CC / 4) + lane] = v;
    }
}

extern "C" void kernel_launch(void* const* d_in, const int* in_sizes, int n_in,
                              void* d_out, int out_size)
{
    const float* input    = (const float*)d_in[0];  // [B,N,C]
    const float* points   = (const float*)d_in[1];  // [B,N,3]
    const float* next_pts = (const float*)d_in[2];  // [B,M,3]
    const int*   indices  = (const int*)  d_in[3];  // [B,M,K]

    float* out_pts  = (float*)d_out;                         // B*M*K*3
    float* out_feat = out_pts + (size_t)BB * MM * KK * 3;    // B*M*K*C

    const int grid = BB * MM;   // 32768 CTAs
    knn_gather_norm_v6_kernel<<<grid, 256>>>(input, points, next_pts, indices,
                                             out_pts, out_feat);
}

// round 7
// speedup vs baseline: 1.3305x; 1.0108x over previous
#include <cuda_runtime.h>
#include <cstdint>

// Problem constants (fixed by the reference)
#define BB 16
#define NN 8192
#define MM 2048
#define KK 32
#define CC 128

// out layout: [pts (B*M*K*3 floats)] ++ [features (B*M*K*C floats)]
//
// One CTA per (b, m). 256 threads = 8 warps. R1 structure (fastest so far)
// with the smem+__syncthreads index stage removed:
//  - each warp loads the 32 indices once, coalesced (lane k = index k),
//    and broadcasts per-row indices with __shfl_sync. No smem, no barrier.
//  - warp 0: normalized relative coords for all K=32 neighbors (lane = k).
//  - warp w copies rows {4w .. 4w+3}, interleaved load->store per row
//    (low MLP_p1 on purpose: front-batched LDGs increase cross-CTA
//    L1tex-queue spread at occ=8 and measurably hurt DRAM utilization).
__global__ __launch_bounds__(256, 8)
void knn_gather_norm_v6_kernel(const float* __restrict__ input,      // [B,N,C]
                               const float* __restrict__ points,     // [B,N,3]
                               const float* __restrict__ next_pts,   // [B,M,3]
                               const int*   __restrict__ indices,    // [B,M,K]
                               float* __restrict__ out_pts,          // [B,M,K,3]
                               float* __restrict__ out_feat)         // [B,M,K,C]
{
    const int bm = blockIdx.x;            // 0 .. B*M-1
    const int b  = bm / MM;

    const int tid  = threadIdx.x;
    const int wid  = tid >> 5;
    const int lane = tid & 31;

    // lane k holds neighbor index k for this bm (one coalesced 128B load)
    const int myidx = __ldg(&indices[(size_t)bm * KK + lane]);

    // ---- pts: warp 0, lane = neighbor k ----
    if (wid == 0) {
        const int idx = myidx;

        const float nx = __ldg(&next_pts[(size_t)bm * 3 + 0]);
        const float ny = __ldg(&next_pts[(size_t)bm * 3 + 1]);
        const float nz = __ldg(&next_pts[(size_t)bm * 3 + 2]);

        const float* p = points + ((size_t)b * NN + (size_t)idx) * 3;
        const float dx = __ldg(&p[0]) - nx;
        const float dy = __ldg(&p[1]) - ny;
        const float dz = __ldg(&p[2]) - nz;

        float mx = dx * dx + dy * dy + dz * dz;
        #pragma unroll
        for (int o = 16; o > 0; o >>= 1)
            mx = fmaxf(mx, __shfl_xor_sync(0xffffffffu, mx, o));

        float maxi = sqrtf(mx);
        if (maxi == 0.0f) maxi = 1.0f;
        const float inv = 1.0f / maxi;

        float* o = out_pts + ((size_t)bm * KK + (size_t)lane) * 3;
        o[0] = dx * inv;
        o[1] = dy * inv;
        o[2] = dz * inv;
    }

    // ---- features: warp wid owns rows {4*wid .. 4*wid+3}, interleaved ----
    const float* __restrict__ in_b = input + (size_t)b * NN * CC;
    float4* __restrict__ of =
        reinterpret_cast<float4*>(out_feat + (size_t)bm * KK * CC);

    #pragma unroll
    for (int j = 0; j < 4; ++j) {
        const int k   = 4 * wid + j;
        const int idx = __shfl_sync(0xffffffffu, myidx, k);
        const float4 v =
            __ldg(reinterpret_cast<const float4*>(in_b + (size_t)idx * CC) + lane);
        of[(size_t)k * (CC / 4) + lane] = v;
    }
}

extern "C" void kernel_launch(void* const* d_in, const int* in_sizes, int n_in,
                              void* d_out, int out_size)
{
    const float* input    = (const float*)d_in[0];  // [B,N,C]
    const float* points   = (const float*)d_in[1];  // [B,N,3]
    const float* next_pts = (const float*)d_in[2];  // [B,M,3]
    const int*   indices  = (const int*)  d_in[3];  // [B,M,K]

    float* out_pts  = (float*)d_out;                         // B*M*K*3
    float* out_feat = out_pts + (size_t)BB * MM * KK * 3;    // B*M*K*C

    const int grid = BB * MM;   // 32768 CTAs
    knn_gather_norm_v6_kernel<<<grid, 256>>>(input, points, next_pts, indices,
                                             out_pts, out_feat);
}